// round 17
// baseline (speedup 1.0000x reference)
#include <cuda_runtime.h>
#include <math.h>

// CliffordBatchNorm, fused persistent kernel + SMEM stash (sm_103a).
// x (B,H,W,C,I) = (32,64,64,64,4) fp32 -> out = A_c * x + d_c per channel.
//
// Phase 1: ascending moments. Slices k=0..7 (lowest 19.4MB, the part L2 must
//          evict) read __ldcs and stashed in SMEM; k>=8 (116MB < 126MB L2)
//          default-cached. Main loop 8-way unrolled (R17) for MLP at the
//          barrier-capped 32 warps/SM.
// Phase 2: blocks 0..63 reduce partials + Cholesky solve -> g_params.
// Phase 3: k DESCENDING: k=kmax..8 from global (L2-hot freshest first,
//          __ldcs, 6-way unrolled), k=7..0 from SMEM (zero DRAM). __stcs.
// Grid barrier; 592 = 148*4 co-resident blocks at 64 regs.

#define C_CH      64
#define NSUM      14
#define NBLOCKS   592          // 148 * 4
#define NTHREADS  256
#define S_STASH   8            // stashed slices per thread (32KB/block)
#define EPS       1e-05f

__device__ float g_partials[C_CH * NBLOCKS * NSUM];   // ~2.1 MB
__device__ float g_params[C_CH * 20];                 // A (16) + d (4)
__device__ unsigned int g_count;
__device__ volatile unsigned int g_gen;

__device__ __forceinline__ void grid_barrier() {
    __syncthreads();
    if (threadIdx.x == 0) {
        __threadfence();
        unsigned int gen = g_gen;
        if (atomicAdd(&g_count, 1u) == NBLOCKS - 1) {
            g_count = 0;
            __threadfence();
            g_gen = gen + 1;
        } else {
            while (g_gen == gen) { }
        }
        __threadfence();
    }
    __syncthreads();
}

__device__ __forceinline__ void acc14(float* __restrict__ acc, float4 v) {
    acc[0] += v.x; acc[1] += v.y; acc[2] += v.z; acc[3] += v.w;
    acc[4] += v.x*v.x; acc[5] += v.x*v.y; acc[6]  += v.x*v.z; acc[7]  += v.x*v.w;
    acc[8] += v.y*v.y; acc[9] += v.y*v.z; acc[10] += v.y*v.w;
    acc[11] += v.z*v.z; acc[12] += v.z*v.w;
    acc[13] += v.w*v.w;
}

__device__ __forceinline__ float4 affine4(const float* __restrict__ P, float4 v) {
    float4 o;
    o.x = fmaf(P[0],  v.x, fmaf(P[1],  v.y, fmaf(P[2],  v.z, fmaf(P[3],  v.w, P[16]))));
    o.y = fmaf(P[4],  v.x, fmaf(P[5],  v.y, fmaf(P[6],  v.z, fmaf(P[7],  v.w, P[17]))));
    o.z = fmaf(P[8],  v.x, fmaf(P[9],  v.y, fmaf(P[10], v.z, fmaf(P[11], v.w, P[18]))));
    o.w = fmaf(P[12], v.x, fmaf(P[13], v.y, fmaf(P[14], v.z, fmaf(P[15], v.w, P[19]))));
    return o;
}

union SmU {
    float sm1[4][C_CH][NSUM];      // phase-1 in-block reduce (14.3KB)
    float sm2[NSUM][NTHREADS];     // phase-2 reduce (14.3KB)
};

__global__ void __launch_bounds__(NTHREADS, 4)
fused_kernel(const float* __restrict__ x,
             const float* __restrict__ weight,   // (I,I,C): [(i*4+j)*64 + c]
             const float* __restrict__ bias,     // (I,C):   [i*64 + c]
             float* __restrict__ out,
             long total_groups, float n_count) {
    const int tid = threadIdx.x;
    const int c   = tid & (C_CH - 1);
    const int sub = tid >> 6;
    const long stride = (long)NBLOCKS * NTHREADS;    // 151552, multiple of 64
    const long g0 = (long)blockIdx.x * NTHREADS + tid;

    __shared__ float4 stash[S_STASH * NTHREADS];     // 32KB, slice-major
    __shared__ SmU smu;                              // 14.3KB

    const float4* __restrict__ x4 = (const float4*)x;

    // ---------------- Phase 1: moments (ascending) -------------------------
    {
        float acc[NSUM];
        #pragma unroll
        for (int k = 0; k < NSUM; k++) acc[k] = 0.f;

        // Stashed slices: lowest addresses, __ldcs, 8 independent loads.
        #pragma unroll
        for (int kk = 0; kk < S_STASH; kk++) {
            float4 v = __ldcs(&x4[g0 + (long)kk * stride]);
            stash[kk * NTHREADS + tid] = v;          // conflict-free (lane-major)
            acc14(acc, v);
        }

        // Remaining slices: default-cached, 8 independent loads in flight.
        long g = g0 + (long)S_STASH * stride;
        for (; g + 7*stride < total_groups; g += 8*stride) {
            float4 v0 = x4[g];
            float4 v1 = x4[g +   stride];
            float4 v2 = x4[g + 2*stride];
            float4 v3 = x4[g + 3*stride];
            float4 v4 = x4[g + 4*stride];
            float4 v5 = x4[g + 5*stride];
            float4 v6 = x4[g + 6*stride];
            float4 v7 = x4[g + 7*stride];
            acc14(acc, v0); acc14(acc, v1); acc14(acc, v2); acc14(acc, v3);
            acc14(acc, v4); acc14(acc, v5); acc14(acc, v6); acc14(acc, v7);
        }
        for (; g < total_groups; g += stride) {
            float4 v = x4[g];
            acc14(acc, v);
        }

        #pragma unroll
        for (int k = 0; k < NSUM; k++) smu.sm1[sub][c][k] = acc[k];
        __syncthreads();

        if (tid < C_CH) {
            float o[NSUM];
            #pragma unroll
            for (int k = 0; k < NSUM; k++)
                o[k] = smu.sm1[0][tid][k] + smu.sm1[1][tid][k]
                     + smu.sm1[2][tid][k] + smu.sm1[3][tid][k];
            float* __restrict__ p = &g_partials[((long)tid * NBLOCKS + blockIdx.x) * NSUM];
            #pragma unroll
            for (int k = 0; k < NSUM; k++) p[k] = o[k];
        }
        __syncthreads();   // sm1 fully consumed before sm2 reuse (union safety)
    }

    grid_barrier();

    // ---------------- Phase 2: reduce + solve (blocks 0..63) ---------------
    if (blockIdx.x < C_CH) {
        const int ch = blockIdx.x;

        float acc[NSUM];
        #pragma unroll
        for (int k = 0; k < NSUM; k++) acc[k] = 0.f;

        for (int g = tid; g < NBLOCKS; g += NTHREADS) {
            const float* __restrict__ p = &g_partials[((long)ch * NBLOCKS + g) * NSUM];
            #pragma unroll
            for (int k = 0; k < NSUM; k++) acc[k] += p[k];
        }
        #pragma unroll
        for (int k = 0; k < NSUM; k++) smu.sm2[k][tid] = acc[k];
        __syncthreads();

        for (int s = 128; s > 0; s >>= 1) {
            if (tid < s) {
                #pragma unroll
                for (int k = 0; k < NSUM; k++) smu.sm2[k][tid] += smu.sm2[k][tid + s];
            }
            __syncthreads();
        }

        if (tid == 0) {
            const float inv_n = 1.0f / n_count;
            float m[4];
            #pragma unroll
            for (int i = 0; i < 4; i++) m[i] = smu.sm2[i][0] * inv_n;

            float cov[4][4];
            const int qidx[4][4] = { {4,5,6,7}, {5,8,9,10}, {6,9,11,12}, {7,10,12,13} };
            #pragma unroll
            for (int i = 0; i < 4; i++)
                #pragma unroll
                for (int j = 0; j < 4; j++)
                    cov[i][j] = smu.sm2[qidx[i][j]][0] * inv_n - m[i]*m[j];
            #pragma unroll
            for (int i = 0; i < 4; i++) cov[i][i] += EPS;

            // Cholesky (lower)
            float L[4][4] = {};
            #pragma unroll
            for (int i = 0; i < 4; i++) {
                #pragma unroll
                for (int j = 0; j <= i; j++) {
                    float sum = cov[i][j];
                    #pragma unroll
                    for (int k = 0; k < 4; k++)
                        if (k < j) sum -= L[i][k]*L[j][k];
                    if (i == j) L[i][i] = sqrtf(sum);
                    else        L[i][j] = sum / L[j][j];
                }
            }

            // Invert lower-triangular L
            float Li[4][4] = {};
            #pragma unroll
            for (int j = 0; j < 4; j++) {
                Li[j][j] = 1.0f / L[j][j];
                #pragma unroll
                for (int i = 0; i < 4; i++) {
                    if (i > j) {
                        float sum = 0.f;
                        #pragma unroll
                        for (int k = 0; k < 4; k++)
                            if (k >= j && k < i) sum += L[i][k]*Li[k][j];
                        Li[i][j] = -sum / L[i][i];
                    }
                }
            }

            // A = W_c @ Li ; d = b_c - A @ m
            float A[4][4], d[4];
            #pragma unroll
            for (int i = 0; i < 4; i++) {
                #pragma unroll
                for (int j = 0; j < 4; j++) {
                    float sum = 0.f;
                    #pragma unroll
                    for (int k = 0; k < 4; k++)
                        sum += weight[(i*4 + k)*C_CH + ch] * Li[k][j];
                    A[i][j] = sum;
                }
            }
            #pragma unroll
            for (int i = 0; i < 4; i++) {
                float s = bias[i*C_CH + ch];
                #pragma unroll
                for (int j = 0; j < 4; j++) s -= A[i][j] * m[j];
                d[i] = s;
            }

            float* __restrict__ P = &g_params[ch * 20];
            #pragma unroll
            for (int i = 0; i < 4; i++)
                #pragma unroll
                for (int j = 0; j < 4; j++)
                    P[i*4 + j] = A[i][j];
            #pragma unroll
            for (int i = 0; i < 4; i++) P[16 + i] = d[i];
        }
    }

    grid_barrier();

    // ---------------- Phase 3: apply (k descending; stash tail) ------------
    {
        float P[20];
        #pragma unroll
        for (int k = 0; k < 20; k++) P[k] = g_params[c * 20 + k];

        float4* __restrict__ o4 = (float4*)out;

        long k = (total_groups - 1 - g0) / stride;       // top slice

        // Global part: k = kmax .. S_STASH, freshest (highest) first, 6-way.
        for (; k >= S_STASH + 5; k -= 6) {
            const long ga = g0 + k*stride;
            const long gb = ga -   stride;
            const long gc = ga - 2*stride;
            const long gd = ga - 3*stride;
            const long ge = ga - 4*stride;
            const long gf = ga - 5*stride;
            float4 va = __ldcs(&x4[ga]);
            float4 vb = __ldcs(&x4[gb]);
            float4 vc = __ldcs(&x4[gc]);
            float4 vd = __ldcs(&x4[gd]);
            float4 ve = __ldcs(&x4[ge]);
            float4 vf = __ldcs(&x4[gf]);
            __stcs(&o4[ga], affine4(P, va));
            __stcs(&o4[gb], affine4(P, vb));
            __stcs(&o4[gc], affine4(P, vc));
            __stcs(&o4[gd], affine4(P, vd));
            __stcs(&o4[ge], affine4(P, ve));
            __stcs(&o4[gf], affine4(P, vf));
        }
        for (; k >= S_STASH; k--) {
            const long g = g0 + k*stride;
            float4 v = __ldcs(&x4[g]);
            __stcs(&o4[g], affine4(P, v));
        }

        // SMEM part: k = S_STASH-1 .. 0 — zero DRAM reads.
        #pragma unroll
        for (int kk = S_STASH - 1; kk >= 0; kk--) {
            float4 v = stash[kk * NTHREADS + tid];
            __stcs(&o4[g0 + (long)kk * stride], affine4(P, v));
        }
    }
}

// ---------------------------------------------------------------------------
extern "C" void kernel_launch(void* const* d_in, const int* in_sizes, int n_in,
                              void* d_out, int out_size) {
    const float* x      = (const float*)d_in[0];   // (B,H,W,C,I) fp32
    const float* weight = (const float*)d_in[1];   // (I,I,C)
    const float* bias   = (const float*)d_in[2];   // (I,C)
    float* out = (float*)d_out;

    const long total_elems  = (long)in_sizes[0];
    const long total_groups = total_elems / 4;              // float4 vectors
    const float n_count     = (float)(total_groups / C_CH); // B*H*W per channel

    fused_kernel<<<NBLOCKS, NTHREADS>>>(x, weight, bias, out, total_groups, n_count);
}